// round 10
// baseline (speedup 1.0000x reference)
#include <cuda_runtime.h>

typedef unsigned long long u64;

#define NTHREADS 128

#define SDIM   3
#define LDIM   4
#define IDIM   3
#define TOT    7
#define SUDIM  10
#define HIDL   64
#define HIDB   32
#define DT_F   0.01f

// ---- constant-memory layout (float offsets; all rows 16B-aligned) ----
#define CW1   0      // 64 x 12: [w0..w9, b1, 0]
#define CW2Q  768    // 64 x 4:  [W2[0][j],W2[1][j],W2[2][j],W2[3][j]]
#define CWZ   1024   // 7 x 12:  [w0..w9, bz, 0]
#define CPHYS 1108   // 3 x 8:   [a0,a1,a2,bm0,bm1,bm2,0,0]
#define CB2   1132   // 4:       b2
#define CWB   1136   // 96 x 8:  [w0..w5, bb1, wb2]
#define CCD   1904   // 3 x 4:   [c0,c1,c2,bb2]
#define CW_TOTAL 1916

__constant__ __align__(16) float cw[CW_TOTAL];
__device__ __align__(16) float g_stage[CW_TOTAL];

__device__ __forceinline__ u64 pack2(float lo, float hi) {
    u64 r; asm("mov.b64 %0, {%1, %2};" : "=l"(r) : "f"(lo), "f"(hi)); return r;
}
__device__ __forceinline__ void unpack2(u64 v, float& lo, float& hi) {
    asm("mov.b64 {%0, %1}, %2;" : "=f"(lo), "=f"(hi) : "l"(v));
}
__device__ __forceinline__ u64 ffma2(u64 a, u64 b, u64 c) {
    u64 d; asm("fma.rn.f32x2 %0, %1, %2, %3;" : "=l"(d) : "l"(a), "l"(b), "l"(c));
    return d;
}
__device__ __forceinline__ float fast_tanh(float x) {
    float r; asm("tanh.approx.f32 %0, %1;" : "=f"(r) : "f"(x)); return r;
}
__device__ __forceinline__ float hsum(u64 v) {
    float lo, hi; unpack2(v, lo, hi); return lo + hi;
}
__device__ __forceinline__ float getlo(u64 v) {
    float lo, hi; unpack2(v, lo, hi); return lo;
}
__device__ __forceinline__ float gethi(u64 v) {
    float lo, hi; unpack2(v, lo, hi); return hi;
}
#define CQUAD(off) (*(const ulonglong2*)(cw + (off)))

// ============================================================================
// Pack kernel: rearrange raw weights into g_stage (then memcpy -> cw)
// ============================================================================
__global__ void pack_weights(const float* __restrict__ gA,  const float* __restrict__ gBm,
                             const float* __restrict__ gC,  const float* __restrict__ gWz,
                             const float* __restrict__ gbz, const float* __restrict__ gW1,
                             const float* __restrict__ gb1, const float* __restrict__ gW2,
                             const float* __restrict__ gb2, const float* __restrict__ gWb1,
                             const float* __restrict__ gbb1,const float* __restrict__ gWb2,
                             const float* __restrict__ gbb2)
{
    int tid = blockIdx.x * blockDim.x + threadIdx.x;
    int nt = gridDim.x * blockDim.x;
    for (int idx = tid; idx < 64 * 12; idx += nt) {
        int r = idx / 12, c = idx % 12;
        g_stage[CW1 + idx] = (c < 10) ? gW1[r * 10 + c] : (c == 10 ? gb1[r] : 0.0f);
    }
    for (int idx = tid; idx < 64 * 4; idx += nt) {
        int j = idx / 4, o = idx % 4;
        g_stage[CW2Q + idx] = gW2[o * HIDL + j];
    }
    for (int idx = tid; idx < 7 * 12; idx += nt) {
        int r = idx / 12, c = idx % 12;
        g_stage[CWZ + idx] = (c < 10) ? gWz[r * 10 + c] : (c == 10 ? gbz[r] : 0.0f);
    }
    for (int idx = tid; idx < 3 * 8; idx += nt) {
        int r = idx / 8, c = idx % 8;
        float v = 0.0f;
        if (c < 3) v = gA[r * 3 + c];
        else if (c < 6) v = gBm[r * 3 + (c - 3)];
        g_stage[CPHYS + idx] = v;
    }
    for (int idx = tid; idx < 4; idx += nt)
        g_stage[CB2 + idx] = gb2[idx];
    for (int idx = tid; idx < 96 * 8; idx += nt) {
        int r = idx / 8, c = idx % 8;
        g_stage[CWB + idx] = (c < 6) ? gWb1[r * 6 + c] : (c == 6 ? gbb1[r] : gWb2[r]);
    }
    for (int idx = tid; idx < 3 * 4; idx += nt) {
        int r = idx / 4, c = idx % 4;
        g_stage[CCD + idx] = (c < 3) ? gC[r * 3 + c] : gbb2[r];
    }
}

// ============================================================================
// Fused compute kernel: bid%3 in {0,1} -> state (2 rows/thr), ==2 -> y (4 rows/thr)
// ============================================================================
__global__ void __launch_bounds__(NTHREADS, 8)
fused_kernel(const float* __restrict__ state,
             const float* __restrict__ u,
             float* __restrict__ out_state,
             float* __restrict__ out_y,
             int Ts,   // = B/2 (state path group stride)
             int Ty)   // = B/4 (y path group stride)
{
    int bid = blockIdx.x;
    int sel = bid % 3;
    int grp = bid / 3;
    if (sel != 2) {
        // ====================================================================
        // STATE path: 2 rows/thread
        // ====================================================================
        int t = (grp * 2 + sel) * NTHREADS + threadIdx.x;
        if (t >= Ts) return;
        int rr[2] = {t, t + Ts};

        u64 sp[2][5];
        #pragma unroll
        for (int r = 0; r < 2; r++) {
            const float* s = state + (size_t)rr[r] * TOT;
            const float* up = u + (size_t)rr[r] * IDIM;
            sp[r][0] = pack2(__ldg(s + 0), __ldg(s + 1));
            sp[r][1] = pack2(__ldg(s + 2), __ldg(s + 3));
            sp[r][2] = pack2(__ldg(s + 4), __ldg(s + 5));
            sp[r][3] = pack2(__ldg(s + 6), __ldg(up + 0));
            sp[r][4] = pack2(__ldg(up + 1), __ldg(up + 2));
        }

        // Phase 1: physics cand + gate rows 0..2 + store
        {
            u64 pm[2];
            #pragma unroll
            for (int r = 0; r < 2; r++)
                pm[r] = pack2(getlo(sp[r][1]), gethi(sp[r][3]));  // (s2, u0)
            #pragma unroll
            for (int i = 0; i < SDIM; i++) {
                ulonglong2 phA = CQUAD(CPHYS + i * 8 + 0);  // (a0,a1),(a2,bm0)
                ulonglong2 phB = CQUAD(CPHYS + i * 8 + 4);  // (bm1,bm2),(0,0)
                ulonglong2 zA = CQUAD(CWZ + i * 12 + 0);
                ulonglong2 zB = CQUAD(CWZ + i * 12 + 4);
                ulonglong2 zC = CQUAD(CWZ + i * 12 + 8);
                #pragma unroll
                for (int r = 0; r < 2; r++) {
                    u64 d = ffma2(phB.x, sp[r][4], 0ull);
                    d = ffma2(phA.y, pm[r], d);
                    d = ffma2(phA.x, sp[r][0], d);
                    float si = (i == 0) ? getlo(sp[r][0])
                             : (i == 1) ? gethi(sp[r][0]) : getlo(sp[r][1]);
                    float c = fmaf(DT_F, hsum(d), si);
                    u64 g = zC.y;
                    g = ffma2(zA.x, sp[r][0], g);
                    g = ffma2(zA.y, sp[r][1], g);
                    g = ffma2(zB.x, sp[r][2], g);
                    g = ffma2(zB.y, sp[r][3], g);
                    g = ffma2(zC.x, sp[r][4], g);
                    float z = fmaf(0.5f, fast_tanh(0.5f * hsum(g)), 0.5f);
                    out_state[(size_t)rr[r] * TOT + i] = fmaf(z, c - si, si);
                }
            }
        }

        // Phase 2: latent MLP with paired accumulators
        u64 acc01[2], acc23[2];
        {
            ulonglong2 b2q = CQUAD(CB2);
            #pragma unroll
            for (int r = 0; r < 2; r++) { acc01[r] = b2q.x; acc23[r] = b2q.y; }
            #pragma unroll 4
            for (int j = 0; j < HIDL; j++) {
                ulonglong2 wA = CQUAD(CW1 + j * 12 + 0);
                ulonglong2 wB = CQUAD(CW1 + j * 12 + 4);
                ulonglong2 wC = CQUAD(CW1 + j * 12 + 8);
                ulonglong2 ww = CQUAD(CW2Q + j * 4);
                u64 t0 = wC.y, t1 = wC.y;
                t0 = ffma2(wA.x, sp[0][0], t0);  t1 = ffma2(wA.x, sp[1][0], t1);
                t0 = ffma2(wA.y, sp[0][1], t0);  t1 = ffma2(wA.y, sp[1][1], t1);
                t0 = ffma2(wB.x, sp[0][2], t0);  t1 = ffma2(wB.x, sp[1][2], t1);
                t0 = ffma2(wB.y, sp[0][3], t0);  t1 = ffma2(wB.y, sp[1][3], t1);
                t0 = ffma2(wC.x, sp[0][4], t0);  t1 = ffma2(wC.x, sp[1][4], t1);
                float h0 = fast_tanh(hsum(t0));
                float h1 = fast_tanh(hsum(t1));
                u64 hh0 = pack2(h0, h0), hh1 = pack2(h1, h1);
                acc01[0] = ffma2(ww.x, hh0, acc01[0]);  acc23[0] = ffma2(ww.y, hh0, acc23[0]);
                acc01[1] = ffma2(ww.x, hh1, acc01[1]);  acc23[1] = ffma2(ww.y, hh1, acc23[1]);
            }
        }

        // Phase 3: gate rows 3..6 + store
        {
            #pragma unroll
            for (int o = 0; o < LDIM; o++) {
                int i = SDIM + o;
                ulonglong2 zA = CQUAD(CWZ + i * 12 + 0);
                ulonglong2 zB = CQUAD(CWZ + i * 12 + 4);
                ulonglong2 zC = CQUAD(CWZ + i * 12 + 8);
                #pragma unroll
                for (int r = 0; r < 2; r++) {
                    float lat = (o == 0) ? gethi(sp[r][1])
                              : (o == 1) ? getlo(sp[r][2])
                              : (o == 2) ? gethi(sp[r][2]) : getlo(sp[r][3]);
                    float dot = (o == 0) ? getlo(acc01[r])
                              : (o == 1) ? gethi(acc01[r])
                              : (o == 2) ? getlo(acc23[r]) : gethi(acc23[r]);
                    float c = fmaf(DT_F, dot, lat);
                    u64 g = zC.y;
                    g = ffma2(zA.x, sp[r][0], g);
                    g = ffma2(zA.y, sp[r][1], g);
                    g = ffma2(zB.x, sp[r][2], g);
                    g = ffma2(zB.y, sp[r][3], g);
                    g = ffma2(zC.x, sp[r][4], g);
                    float z = fmaf(0.5f, fast_tanh(0.5f * hsum(g)), 0.5f);
                    out_state[(size_t)rr[r] * TOT + i] = fmaf(z, c - lat, lat);
                }
            }
        }
    } else {
        // ====================================================================
        // Y path: 4 rows/thread, within-row pairing
        // ====================================================================
        int t = grp * NTHREADS + threadIdx.x;
        if (t >= Ty) return;
        int rr[4] = {t, t + Ty, t + 2 * Ty, t + 3 * Ty};

        // bp[r]: (s0,s1), (s2,u0), (u1,u2)
        u64 bp[4][3];
        u64 s2one[4];
        #pragma unroll
        for (int r = 0; r < 4; r++) {
            const float* s = state + (size_t)rr[r] * TOT;
            const float* up = u + (size_t)rr[r] * IDIM;
            bp[r][0] = pack2(__ldg(s + 0), __ldg(s + 1));
            bp[r][1] = pack2(__ldg(s + 2), __ldg(up + 0));
            bp[r][2] = pack2(__ldg(up + 1), __ldg(up + 2));
            s2one[r] = pack2(getlo(bp[r][1]), 1.0f);   // (s2, 1)
        }

        #pragma unroll
        for (int k = 0; k < SDIM; k++) {
            ulonglong2 cc = CQUAD(CCD + k * 4);   // (c0,c1),(c2,bb2)
            float res[4];
            #pragma unroll
            for (int r = 0; r < 4; r++)
                res[r] = hsum(ffma2(cc.y, s2one[r], ffma2(cc.x, bp[r][0], 0ull)));
            #pragma unroll 4
            for (int j = 0; j < HIDB; j++) {
                int row = k * HIDB + j;
                ulonglong2 wA = CQUAD(CWB + row * 8 + 0);  // (w0,w1),(w2,w3)
                ulonglong2 wB = CQUAD(CWB + row * 8 + 4);  // (w4,w5),(bb1,wb2)
                u64 tinit = pack2(getlo(wB.y), 0.0f);
                float wb2 = gethi(wB.y);
                u64 t0 = ffma2(wA.x, bp[0][0], tinit);
                u64 t1 = ffma2(wA.x, bp[1][0], tinit);
                u64 t2 = ffma2(wA.x, bp[2][0], tinit);
                u64 t3 = ffma2(wA.x, bp[3][0], tinit);
                t0 = ffma2(wA.y, bp[0][1], t0);
                t1 = ffma2(wA.y, bp[1][1], t1);
                t2 = ffma2(wA.y, bp[2][1], t2);
                t3 = ffma2(wA.y, bp[3][1], t3);
                t0 = ffma2(wB.x, bp[0][2], t0);
                t1 = ffma2(wB.x, bp[1][2], t1);
                t2 = ffma2(wB.x, bp[2][2], t2);
                t3 = ffma2(wB.x, bp[3][2], t3);
                res[0] = fmaf(wb2, fast_tanh(hsum(t0)), res[0]);
                res[1] = fmaf(wb2, fast_tanh(hsum(t1)), res[1]);
                res[2] = fmaf(wb2, fast_tanh(hsum(t2)), res[2]);
                res[3] = fmaf(wb2, fast_tanh(hsum(t3)), res[3]);
            }
            #pragma unroll
            for (int r = 0; r < 4; r++)
                out_y[(size_t)rr[r] * SDIM + k] = res[r];
        }
    }
}

extern "C" void kernel_launch(void* const* d_in, const int* in_sizes, int n_in,
                              void* d_out, int out_size) {
    const float* state = (const float*)d_in[0];
    const float* u     = (const float*)d_in[1];
    const float* A     = (const float*)d_in[2];
    const float* Bm    = (const float*)d_in[3];
    const float* C     = (const float*)d_in[4];
    const float* Wz    = (const float*)d_in[5];
    const float* bz    = (const float*)d_in[6];
    const float* W1    = (const float*)d_in[7];
    const float* b1    = (const float*)d_in[8];
    const float* W2    = (const float*)d_in[9];
    const float* b2    = (const float*)d_in[10];
    const float* Wb1   = (const float*)d_in[11];
    const float* bb1   = (const float*)d_in[12];
    const float* Wb2   = (const float*)d_in[13];
    const float* bb2   = (const float*)d_in[14];

    int B = in_sizes[0] / TOT;
    float* out       = (float*)d_out;
    float* out_state = out;                      // [B, 7]
    float* out_y     = out + (size_t)B * TOT;    // [B, 3]

    // 1) pack weights into staging, 2) memcpy D2D into __constant__
    pack_weights<<<8, 256>>>(A, Bm, C, Wz, bz, W1, b1, W2, b2,
                             Wb1, bb1, Wb2, bb2);
    void* cw_addr = nullptr;
    void* st_addr = nullptr;
    cudaGetSymbolAddress(&cw_addr, cw);
    cudaGetSymbolAddress(&st_addr, g_stage);
    cudaMemcpyAsync(cw_addr, st_addr, CW_TOTAL * sizeof(float),
                    cudaMemcpyDeviceToDevice);

    // 3) fused compute: B = 2^21 -> state blocks = B/2/128 = 8192,
    //    y blocks = B/4/128 = 4096, exactly 2:1 -> grid = 12288, bid%3 select.
    int Ts = B / 2;
    int Ty = B / 4;
    int state_blocks = (Ts + NTHREADS - 1) / NTHREADS;
    int y_blocks     = (Ty + NTHREADS - 1) / NTHREADS;
    int grid = state_blocks + y_blocks;
    fused_kernel<<<grid, NTHREADS>>>(state, u, out_state, out_y, Ts, Ty);
}

// round 11
// speedup vs baseline: 1.1435x; 1.1435x over previous
#include <cuda_runtime.h>

typedef unsigned long long u64;

#define NTHREADS 128

#define SDIM   3
#define LDIM   4
#define IDIM   3
#define TOT    7
#define SUDIM  10
#define HIDL   64
#define HIDB   32
#define DT_F   0.01f

// ---- constant-memory layout (float offsets; all rows 16B-aligned) ----
#define CW1   0      // 64 x 12: [w0..w9, b1, 0]
#define CW2Q  768    // 64 x 4:  [W2[0][j],W2[1][j],W2[2][j],W2[3][j]]
#define CWZ   1024   // 7 x 12:  [w0..w9, bz, 0]
#define CPHYS 1108   // 3 x 8:   [a0,a1,a2,bm0,bm1,bm2,0,0]
#define CB2   1132   // 4:       b2
#define CWB   1136   // 96 x 8:  [w0..w5, bb1, wb2]
#define CCD   1904   // 3 x 4:   [c0,c1,c2,bb2]
#define CW_TOTAL 1916

__constant__ __align__(16) float cw[CW_TOTAL];
__device__ __align__(16) float g_stage[CW_TOTAL];

__device__ __forceinline__ u64 pack2(float lo, float hi) {
    u64 r; asm("mov.b64 %0, {%1, %2};" : "=l"(r) : "f"(lo), "f"(hi)); return r;
}
__device__ __forceinline__ void unpack2(u64 v, float& lo, float& hi) {
    asm("mov.b64 {%0, %1}, %2;" : "=f"(lo), "=f"(hi) : "l"(v));
}
__device__ __forceinline__ u64 ffma2(u64 a, u64 b, u64 c) {
    u64 d; asm("fma.rn.f32x2 %0, %1, %2, %3;" : "=l"(d) : "l"(a), "l"(b), "l"(c));
    return d;
}
__device__ __forceinline__ float fast_tanh(float x) {
    float r; asm("tanh.approx.f32 %0, %1;" : "=f"(r) : "f"(x)); return r;
}
__device__ __forceinline__ float hsum(u64 v) {
    float lo, hi; unpack2(v, lo, hi); return lo + hi;
}
__device__ __forceinline__ float getlo(u64 v) {
    float lo, hi; unpack2(v, lo, hi); return lo;
}
__device__ __forceinline__ float gethi(u64 v) {
    float lo, hi; unpack2(v, lo, hi); return hi;
}
#define CQUAD(off) (*(const ulonglong2*)(cw + (off)))

// ============================================================================
// Pack kernel: rearrange raw weights into g_stage (then memcpy -> cw)
// ============================================================================
__global__ void pack_weights(const float* __restrict__ gA,  const float* __restrict__ gBm,
                             const float* __restrict__ gC,  const float* __restrict__ gWz,
                             const float* __restrict__ gbz, const float* __restrict__ gW1,
                             const float* __restrict__ gb1, const float* __restrict__ gW2,
                             const float* __restrict__ gb2, const float* __restrict__ gWb1,
                             const float* __restrict__ gbb1,const float* __restrict__ gWb2,
                             const float* __restrict__ gbb2)
{
    int tid = blockIdx.x * blockDim.x + threadIdx.x;
    int nt = gridDim.x * blockDim.x;
    for (int idx = tid; idx < 64 * 12; idx += nt) {
        int r = idx / 12, c = idx % 12;
        g_stage[CW1 + idx] = (c < 10) ? gW1[r * 10 + c] : (c == 10 ? gb1[r] : 0.0f);
    }
    for (int idx = tid; idx < 64 * 4; idx += nt) {
        int j = idx / 4, o = idx % 4;
        g_stage[CW2Q + idx] = gW2[o * HIDL + j];
    }
    for (int idx = tid; idx < 7 * 12; idx += nt) {
        int r = idx / 12, c = idx % 12;
        g_stage[CWZ + idx] = (c < 10) ? gWz[r * 10 + c] : (c == 10 ? gbz[r] : 0.0f);
    }
    for (int idx = tid; idx < 3 * 8; idx += nt) {
        int r = idx / 8, c = idx % 8;
        float v = 0.0f;
        if (c < 3) v = gA[r * 3 + c];
        else if (c < 6) v = gBm[r * 3 + (c - 3)];
        g_stage[CPHYS + idx] = v;
    }
    for (int idx = tid; idx < 4; idx += nt)
        g_stage[CB2 + idx] = gb2[idx];
    for (int idx = tid; idx < 96 * 8; idx += nt) {
        int r = idx / 8, c = idx % 8;
        g_stage[CWB + idx] = (c < 6) ? gWb1[r * 6 + c] : (c == 6 ? gbb1[r] : gWb2[r]);
    }
    for (int idx = tid; idx < 3 * 4; idx += nt) {
        int r = idx / 4, c = idx % 4;
        g_stage[CCD + idx] = (c < 3) ? gC[r * 3 + c] : gbb2[r];
    }
}

// ============================================================================
// Fused compute kernel: even blocks -> next_state, odd blocks -> y
// (both paths 4 rows/thread; occupancy forced to 7 blocks/SM)
// ============================================================================
__global__ void __launch_bounds__(NTHREADS, 7)
fused_kernel(const float* __restrict__ state,
             const float* __restrict__ u,
             float* __restrict__ out_state,
             float* __restrict__ out_y,
             int T)   // T = B/4 for both paths
{
    if ((blockIdx.x & 1) == 0) {
        // ====================================================================
        // STATE path: 4 rows/thread
        // ====================================================================
        int t = (blockIdx.x >> 1) * NTHREADS + threadIdx.x;
        if (t >= T) return;
        int rr[4] = {t, t + T, t + 2 * T, t + 3 * T};

        u64 sp[4][5];
        #pragma unroll
        for (int r = 0; r < 4; r++) {
            const float* s = state + (size_t)rr[r] * TOT;
            const float* up = u + (size_t)rr[r] * IDIM;
            sp[r][0] = pack2(__ldg(s + 0), __ldg(s + 1));
            sp[r][1] = pack2(__ldg(s + 2), __ldg(s + 3));
            sp[r][2] = pack2(__ldg(s + 4), __ldg(s + 5));
            sp[r][3] = pack2(__ldg(s + 6), __ldg(up + 0));
            sp[r][4] = pack2(__ldg(up + 1), __ldg(up + 2));
        }

        // Phase 1: physics cand + gate rows 0..2 + store
        {
            #pragma unroll
            for (int i = 0; i < SDIM; i++) {
                ulonglong2 phA = CQUAD(CPHYS + i * 8 + 0);  // (a0,a1),(a2,bm0)
                ulonglong2 phB = CQUAD(CPHYS + i * 8 + 4);  // (bm1,bm2),(0,0)
                ulonglong2 zA = CQUAD(CWZ + i * 12 + 0);
                ulonglong2 zB = CQUAD(CWZ + i * 12 + 4);
                ulonglong2 zC = CQUAD(CWZ + i * 12 + 8);
                #pragma unroll
                for (int r = 0; r < 4; r++) {
                    u64 pm = pack2(getlo(sp[r][1]), gethi(sp[r][3]));  // (s2,u0)
                    u64 d = ffma2(phB.x, sp[r][4], 0ull);
                    d = ffma2(phA.y, pm, d);
                    d = ffma2(phA.x, sp[r][0], d);
                    float si = (i == 0) ? getlo(sp[r][0])
                             : (i == 1) ? gethi(sp[r][0]) : getlo(sp[r][1]);
                    float c = fmaf(DT_F, hsum(d), si);
                    u64 g = zC.y;
                    g = ffma2(zA.x, sp[r][0], g);
                    g = ffma2(zA.y, sp[r][1], g);
                    g = ffma2(zB.x, sp[r][2], g);
                    g = ffma2(zB.y, sp[r][3], g);
                    g = ffma2(zC.x, sp[r][4], g);
                    float z = fmaf(0.5f, fast_tanh(0.5f * hsum(g)), 0.5f);
                    out_state[(size_t)rr[r] * TOT + i] = fmaf(z, c - si, si);
                }
            }
        }

        // Phase 2: latent MLP with paired accumulators
        u64 acc01[4], acc23[4];
        {
            ulonglong2 b2q = CQUAD(CB2);   // (b2_0,b2_1),(b2_2,b2_3)
            #pragma unroll
            for (int r = 0; r < 4; r++) { acc01[r] = b2q.x; acc23[r] = b2q.y; }
            #pragma unroll 4
            for (int j = 0; j < HIDL; j++) {
                ulonglong2 wA = CQUAD(CW1 + j * 12 + 0);  // (w0,w1),(w2,w3)
                ulonglong2 wB = CQUAD(CW1 + j * 12 + 4);  // (w4,w5),(w6,w7)
                ulonglong2 wC = CQUAD(CW1 + j * 12 + 8);  // (w8,w9),(b1,0)
                ulonglong2 ww = CQUAD(CW2Q + j * 4);      // (W2_0,W2_1),(W2_2,W2_3)
                u64 t0 = wC.y, t1 = wC.y, t2 = wC.y, t3 = wC.y;
                t0 = ffma2(wA.x, sp[0][0], t0);  t1 = ffma2(wA.x, sp[1][0], t1);
                t2 = ffma2(wA.x, sp[2][0], t2);  t3 = ffma2(wA.x, sp[3][0], t3);
                t0 = ffma2(wA.y, sp[0][1], t0);  t1 = ffma2(wA.y, sp[1][1], t1);
                t2 = ffma2(wA.y, sp[2][1], t2);  t3 = ffma2(wA.y, sp[3][1], t3);
                t0 = ffma2(wB.x, sp[0][2], t0);  t1 = ffma2(wB.x, sp[1][2], t1);
                t2 = ffma2(wB.x, sp[2][2], t2);  t3 = ffma2(wB.x, sp[3][2], t3);
                t0 = ffma2(wB.y, sp[0][3], t0);  t1 = ffma2(wB.y, sp[1][3], t1);
                t2 = ffma2(wB.y, sp[2][3], t2);  t3 = ffma2(wB.y, sp[3][3], t3);
                t0 = ffma2(wC.x, sp[0][4], t0);  t1 = ffma2(wC.x, sp[1][4], t1);
                t2 = ffma2(wC.x, sp[2][4], t2);  t3 = ffma2(wC.x, sp[3][4], t3);
                float h0 = fast_tanh(hsum(t0));
                float h1 = fast_tanh(hsum(t1));
                float h2 = fast_tanh(hsum(t2));
                float h3 = fast_tanh(hsum(t3));
                u64 hh0 = pack2(h0, h0), hh1 = pack2(h1, h1);
                u64 hh2 = pack2(h2, h2), hh3 = pack2(h3, h3);
                acc01[0] = ffma2(ww.x, hh0, acc01[0]);  acc23[0] = ffma2(ww.y, hh0, acc23[0]);
                acc01[1] = ffma2(ww.x, hh1, acc01[1]);  acc23[1] = ffma2(ww.y, hh1, acc23[1]);
                acc01[2] = ffma2(ww.x, hh2, acc01[2]);  acc23[2] = ffma2(ww.y, hh2, acc23[2]);
                acc01[3] = ffma2(ww.x, hh3, acc01[3]);  acc23[3] = ffma2(ww.y, hh3, acc23[3]);
            }
        }

        // Phase 3: gate rows 3..6 + store
        {
            #pragma unroll
            for (int o = 0; o < LDIM; o++) {
                int i = SDIM + o;
                ulonglong2 zA = CQUAD(CWZ + i * 12 + 0);
                ulonglong2 zB = CQUAD(CWZ + i * 12 + 4);
                ulonglong2 zC = CQUAD(CWZ + i * 12 + 8);
                #pragma unroll
                for (int r = 0; r < 4; r++) {
                    float lat = (o == 0) ? gethi(sp[r][1])
                              : (o == 1) ? getlo(sp[r][2])
                              : (o == 2) ? gethi(sp[r][2]) : getlo(sp[r][3]);
                    float dot = (o == 0) ? getlo(acc01[r])
                              : (o == 1) ? gethi(acc01[r])
                              : (o == 2) ? getlo(acc23[r]) : gethi(acc23[r]);
                    float c = fmaf(DT_F, dot, lat);
                    u64 g = zC.y;
                    g = ffma2(zA.x, sp[r][0], g);
                    g = ffma2(zA.y, sp[r][1], g);
                    g = ffma2(zB.x, sp[r][2], g);
                    g = ffma2(zB.y, sp[r][3], g);
                    g = ffma2(zC.x, sp[r][4], g);
                    float z = fmaf(0.5f, fast_tanh(0.5f * hsum(g)), 0.5f);
                    out_state[(size_t)rr[r] * TOT + i] = fmaf(z, c - lat, lat);
                }
            }
        }
    } else {
        // ====================================================================
        // Y path: 4 rows/thread, within-row pairing, paired res accumulators
        // ====================================================================
        int t = (blockIdx.x >> 1) * NTHREADS + threadIdx.x;
        if (t >= T) return;
        int rr[4] = {t, t + T, t + 2 * T, t + 3 * T};

        // bp[r]: (s0,s1), (s2,u0), (u1,u2)
        u64 bp[4][3];
        u64 s2one[4];
        #pragma unroll
        for (int r = 0; r < 4; r++) {
            const float* s = state + (size_t)rr[r] * TOT;
            const float* up = u + (size_t)rr[r] * IDIM;
            bp[r][0] = pack2(__ldg(s + 0), __ldg(s + 1));
            bp[r][1] = pack2(__ldg(s + 2), __ldg(up + 0));
            bp[r][2] = pack2(__ldg(up + 1), __ldg(up + 2));
            s2one[r] = pack2(getlo(bp[r][1]), 1.0f);   // (s2, 1)
        }

        #pragma unroll
        for (int k = 0; k < SDIM; k++) {
            ulonglong2 cc = CQUAD(CCD + k * 4);   // (c0,c1),(c2,bb2)
            // res01 = (res_row0, res_row1), res23 = (res_row2, res_row3)
            u64 res01, res23;
            {
                float r0 = hsum(ffma2(cc.y, s2one[0], ffma2(cc.x, bp[0][0], 0ull)));
                float r1 = hsum(ffma2(cc.y, s2one[1], ffma2(cc.x, bp[1][0], 0ull)));
                float r2 = hsum(ffma2(cc.y, s2one[2], ffma2(cc.x, bp[2][0], 0ull)));
                float r3 = hsum(ffma2(cc.y, s2one[3], ffma2(cc.x, bp[3][0], 0ull)));
                res01 = pack2(r0, r1);
                res23 = pack2(r2, r3);
            }
            #pragma unroll 4
            for (int j = 0; j < HIDB; j++) {
                int row = k * HIDB + j;
                ulonglong2 wA = CQUAD(CWB + row * 8 + 0);  // (w0,w1),(w2,w3)
                ulonglong2 wB = CQUAD(CWB + row * 8 + 4);  // (w4,w5),(bb1,wb2)
                u64 tinit = pack2(getlo(wB.y), 0.0f);
                float wb2 = gethi(wB.y);
                u64 wb2p = pack2(wb2, wb2);
                u64 t0 = ffma2(wA.x, bp[0][0], tinit);
                u64 t1 = ffma2(wA.x, bp[1][0], tinit);
                u64 t2 = ffma2(wA.x, bp[2][0], tinit);
                u64 t3 = ffma2(wA.x, bp[3][0], tinit);
                t0 = ffma2(wA.y, bp[0][1], t0);
                t1 = ffma2(wA.y, bp[1][1], t1);
                t2 = ffma2(wA.y, bp[2][1], t2);
                t3 = ffma2(wA.y, bp[3][1], t3);
                t0 = ffma2(wB.x, bp[0][2], t0);
                t1 = ffma2(wB.x, bp[1][2], t1);
                t2 = ffma2(wB.x, bp[2][2], t2);
                t3 = ffma2(wB.x, bp[3][2], t3);
                u64 h01 = pack2(fast_tanh(hsum(t0)), fast_tanh(hsum(t1)));
                u64 h23 = pack2(fast_tanh(hsum(t2)), fast_tanh(hsum(t3)));
                res01 = ffma2(wb2p, h01, res01);
                res23 = ffma2(wb2p, h23, res23);
            }
            float y0, y1, y2, y3;
            unpack2(res01, y0, y1);  unpack2(res23, y2, y3);
            out_y[(size_t)rr[0] * SDIM + k] = y0;
            out_y[(size_t)rr[1] * SDIM + k] = y1;
            out_y[(size_t)rr[2] * SDIM + k] = y2;
            out_y[(size_t)rr[3] * SDIM + k] = y3;
        }
    }
}

extern "C" void kernel_launch(void* const* d_in, const int* in_sizes, int n_in,
                              void* d_out, int out_size) {
    const float* state = (const float*)d_in[0];
    const float* u     = (const float*)d_in[1];
    const float* A     = (const float*)d_in[2];
    const float* Bm    = (const float*)d_in[3];
    const float* C     = (const float*)d_in[4];
    const float* Wz    = (const float*)d_in[5];
    const float* bz    = (const float*)d_in[6];
    const float* W1    = (const float*)d_in[7];
    const float* b1    = (const float*)d_in[8];
    const float* W2    = (const float*)d_in[9];
    const float* b2    = (const float*)d_in[10];
    const float* Wb1   = (const float*)d_in[11];
    const float* bb1   = (const float*)d_in[12];
    const float* Wb2   = (const float*)d_in[13];
    const float* bb2   = (const float*)d_in[14];

    int B = in_sizes[0] / TOT;
    float* out       = (float*)d_out;
    float* out_state = out;                      // [B, 7]
    float* out_y     = out + (size_t)B * TOT;    // [B, 3]

    // 1) pack weights into staging, 2) memcpy D2D into __constant__
    pack_weights<<<8, 256>>>(A, Bm, C, Wz, bz, W1, b1, W2, b2,
                             Wb1, bb1, Wb2, bb2);
    void* cw_addr = nullptr;
    void* st_addr = nullptr;
    cudaGetSymbolAddress(&cw_addr, cw);
    cudaGetSymbolAddress(&st_addr, g_stage);
    cudaMemcpyAsync(cw_addr, st_addr, CW_TOTAL * sizeof(float),
                    cudaMemcpyDeviceToDevice);

    // 3) fused compute
    int T = B / 4;
    int blocks_per_path = (T + NTHREADS - 1) / NTHREADS;
    int grid = blocks_per_path * 2;
    fused_kernel<<<grid, NTHREADS>>>(state, u, out_state, out_y, T);
}